// round 9
// baseline (speedup 1.0000x reference)
#include <cuda_runtime.h>
#include <cuda_bf16.h>
#include <math.h>
#include <stdint.h>

#define BB 16
#define DD 128
#define LC 2048
#define LQ 512
#define NEGF (-1e30f)

// ---- scratch ----
__device__ float g_S[(size_t)BB * LC * LQ];
__device__ float g_A[(size_t)BB * LC * DD];
__device__ float g_Bm[(size_t)BB * LC * DD];
__device__ float g_V2[(size_t)BB * LQ * DD];
__device__ float g_V2p[(size_t)4 * BB * LQ * DD];
__device__ float g_sub0[BB * LC];
__device__ float g_sub1[BB * LQ];
__device__ float g_rmax[BB * LC], g_rinv[BB * LC];
__device__ float g_cmax[BB * LQ], g_cinv[BB * LQ];
__device__ float g_cpm[4 * BB * LQ], g_cps[4 * BB * LQ];

// smem: 4 packed-bf16x2 tiles uint32[16][TSTR2] + AUX floats[768]
#define TSTR2 136
#define TILE_U (16 * TSTR2)
#define SMEM_BYTES ((4 * TILE_U + 768) * 4)

// split v into bf16 hi/lo pair, packed 2-wide (lo half = v0, hi half = v1)
__device__ __forceinline__ void split2(float v0, float v1, uint32_t& H, uint32_t& L) {
    asm("cvt.rn.satfinite.bf16x2.f32 %0, %1, %2;" : "=r"(H) : "f"(v1), "f"(v0));
    float h0, h1;
    asm("{ .reg .b16 lo, hi;\n\t"
        "  mov.b32 {lo, hi}, %2;\n\t"
        "  cvt.f32.bf16 %0, lo;\n\t"
        "  cvt.f32.bf16 %1, hi; }"
        : "=f"(h0), "=f"(h1) : "r"(H));
    asm("cvt.rn.satfinite.bf16x2.f32 %0, %1, %2;" : "=r"(L) : "f"(v1 - h1), "f"(v0 - h0));
}

#define MMA16(c, a, b0, b1)                                                   \
    asm volatile(                                                             \
        "mma.sync.aligned.m16n8k16.row.col.f32.bf16.bf16.f32 "                \
        "{%0,%1,%2,%3}, {%4,%5,%6,%7}, {%8,%9}, {%0,%1,%2,%3};"               \
        : "+f"((c)[0]), "+f"((c)[1]), "+f"((c)[2]), "+f"((c)[3])              \
        : "r"((a)[0]), "r"((a)[1]), "r"((a)[2]), "r"((a)[3]),                 \
          "r"(b0), "r"(b1))

// one BK=32 chunk; warp tile 32(m) x 64(n); tiles are [kpair][row] uint32
__device__ __forceinline__ void mma_chunk(const uint32_t* AH, const uint32_t* AL,
                                          const uint32_t* BH, const uint32_t* BL,
                                          float acc[2][8][4],
                                          int mbase, int nbase, int lane) {
    int lq = lane >> 2, kq = lane & 3;
    #pragma unroll
    for (int s = 0; s < 2; s++) {
        int kb = s * 8;
        uint32_t ah[2][4], al[2][4];
        #pragma unroll
        for (int ma = 0; ma < 2; ma++) {
            int r = mbase + 16 * ma + lq;
            ah[ma][0] = AH[(kb + kq) * TSTR2 + r];
            ah[ma][1] = AH[(kb + kq) * TSTR2 + r + 8];
            ah[ma][2] = AH[(kb + kq + 4) * TSTR2 + r];
            ah[ma][3] = AH[(kb + kq + 4) * TSTR2 + r + 8];
            al[ma][0] = AL[(kb + kq) * TSTR2 + r];
            al[ma][1] = AL[(kb + kq) * TSTR2 + r + 8];
            al[ma][2] = AL[(kb + kq + 4) * TSTR2 + r];
            al[ma][3] = AL[(kb + kq + 4) * TSTR2 + r + 8];
        }
        #pragma unroll
        for (int na = 0; na < 8; na++) {
            int c0 = nbase + 8 * na + lq;
            uint32_t bh0 = BH[(kb + kq) * TSTR2 + c0];
            uint32_t bh1 = BH[(kb + kq + 4) * TSTR2 + c0];
            uint32_t bl0 = BL[(kb + kq) * TSTR2 + c0];
            uint32_t bl1 = BL[(kb + kq + 4) * TSTR2 + c0];
            #pragma unroll
            for (int ma = 0; ma < 2; ma++) {
                MMA16(acc[ma][na], ah[ma], bh0, bh1);
                MMA16(acc[ma][na], ah[ma], bl0, bl1);
                MMA16(acc[ma][na], al[ma], bh0, bh1);
            }
        }
    }
}

// ============================================================
// K0: sub0 / sub1
// ============================================================
__global__ void k_sub(const float* __restrict__ C, const float* __restrict__ Q,
                      const float* __restrict__ w4C, const float* __restrict__ w4Q,
                      const float* __restrict__ bias) {
    int t = blockIdx.x * blockDim.x + threadIdx.x;
    const int totC = BB * LC;
    if (t < totC) {
        int b = t / LC, c = t % LC;
        const float* Cp = C + (size_t)b * DD * LC + c;
        float s = 0.f;
        #pragma unroll 8
        for (int d = 0; d < DD; d++) s += Cp[(size_t)d * LC] * w4C[d];
        g_sub0[t] = s;
    } else if (t < totC + BB * LQ) {
        int u = t - totC;
        int b = u / LQ, q = u % LQ;
        const float* Qp = Q + (size_t)b * DD * LQ + q;
        float s = bias[0];
        #pragma unroll 8
        for (int d = 0; d < DD; d++) s += Qp[(size_t)d * LQ] * w4Q[d];
        g_sub1[u] = s;
    }
}

// ============================================================
// K1: S = (C*w)^T Q + sub0 + sub1  [m=c, n=q, k=d(128)]
// ============================================================
__global__ __launch_bounds__(256, 2) void k_scores(const float* __restrict__ C,
                                                   const float* __restrict__ Q,
                                                   const float* __restrict__ w4mlu) {
    extern __shared__ uint32_t smu[];
    uint32_t* TAH = smu;
    uint32_t* TAL = TAH + TILE_U;
    uint32_t* TBH = TAL + TILE_U;
    uint32_t* TBL = TBH + TILE_U;
    float* AUX = (float*)(TBL + TILE_U);
    int tid = threadIdx.x, wid = tid >> 5, lane = tid & 31;
    int b = blockIdx.z, cb = blockIdx.y * 128, qb = blockIdx.x * 128;
    int mbase = (wid >> 1) * 32, nbase = (wid & 1) * 64;
    const float* Cb = C + (size_t)b * DD * LC + cb;
    const float* Qb = Q + (size_t)b * DD * LQ + qb;

    if (tid < 128) {
        AUX[tid] = g_sub0[b * LC + cb + tid];
        AUX[128 + tid] = g_sub1[b * LQ + qb + tid];
    }

    float acc[2][8][4];
    #pragma unroll
    for (int i = 0; i < 2; i++)
        #pragma unroll
        for (int j = 0; j < 8; j++)
            #pragma unroll
            for (int r = 0; r < 4; r++) acc[i][j][r] = 0.f;

    for (int k0 = 0; k0 < DD; k0 += 32) {
        #pragma unroll
        for (int it = 0; it < 4; it++) {
            int idx = tid + it * 256;          // 0..1023
            int kp = idx & 15, cp = idx >> 4;  // kpair, col-pair
            int c2 = cp * 2;
            int d0 = k0 + 2 * kp;
            float w0 = w4mlu[d0], w1 = w4mlu[d0 + 1];
            float2 a0 = *(const float2*)(Cb + (size_t)d0 * LC + c2);
            float2 a1 = *(const float2*)(Cb + (size_t)(d0 + 1) * LC + c2);
            uint32_t H, L;
            split2(a0.x * w0, a1.x * w1, H, L);
            TAH[kp * TSTR2 + c2] = H; TAL[kp * TSTR2 + c2] = L;
            split2(a0.y * w0, a1.y * w1, H, L);
            TAH[kp * TSTR2 + c2 + 1] = H; TAL[kp * TSTR2 + c2 + 1] = L;
            float2 q0 = *(const float2*)(Qb + (size_t)d0 * LQ + c2);
            float2 q1 = *(const float2*)(Qb + (size_t)(d0 + 1) * LQ + c2);
            split2(q0.x, q1.x, H, L);
            TBH[kp * TSTR2 + c2] = H; TBL[kp * TSTR2 + c2] = L;
            split2(q0.y, q1.y, H, L);
            TBH[kp * TSTR2 + c2 + 1] = H; TBL[kp * TSTR2 + c2 + 1] = L;
        }
        __syncthreads();
        mma_chunk(TAH, TAL, TBH, TBL, acc, mbase, nbase, lane);
        __syncthreads();
    }

    int lq = lane >> 2, kq = lane & 3;
    #pragma unroll
    for (int ma = 0; ma < 2; ma++)
        #pragma unroll
        for (int na = 0; na < 8; na++) {
            int r = mbase + 16 * ma + lq;
            int col = nbase + 8 * na + kq * 2;
            float s1a = AUX[128 + col], s1b = AUX[128 + col + 1];
            float s0a = AUX[r], s0b = AUX[r + 8];
            float* o0 = g_S + ((size_t)b * LC + cb + r) * LQ + qb + col;
            float* o1 = g_S + ((size_t)b * LC + cb + r + 8) * LQ + qb + col;
            *(float2*)o0 = make_float2(acc[ma][na][0] + s0a + s1a,
                                       acc[ma][na][1] + s0a + s1b);
            *(float2*)o1 = make_float2(acc[ma][na][2] + s0b + s1a,
                                       acc[ma][na][3] + s0b + s1b);
        }
}

// ============================================================
// stats
// ============================================================
__global__ void k_rowstats(const int* __restrict__ Qmask) {
    int w = blockIdx.x * 8 + (threadIdx.x >> 5);
    int lane = threadIdx.x & 31;
    if (w >= BB * LC) return;
    int b = w / LC;
    const float* Sp = g_S + (size_t)w * LQ;
    const int* qm = Qmask + b * LQ;
    float vals[16], m = -INFINITY;
    #pragma unroll
    for (int i = 0; i < 16; i++) {
        int q = lane + 32 * i;
        float v = Sp[q];
        if (!qm[q]) v += NEGF;
        vals[i] = v; m = fmaxf(m, v);
    }
    #pragma unroll
    for (int o = 16; o > 0; o >>= 1) m = fmaxf(m, __shfl_xor_sync(~0u, m, o));
    float s = 0.f;
    #pragma unroll
    for (int i = 0; i < 16; i++) s += __expf(vals[i] - m);
    #pragma unroll
    for (int o = 16; o > 0; o >>= 1) s += __shfl_xor_sync(~0u, s, o);
    if (lane == 0) { g_rmax[w] = m; g_rinv[w] = 1.f / s; }
}

__global__ void k_colstats_part(const int* __restrict__ Cmask) {
    __shared__ float sm[8][33], ss[8][33];
    __shared__ float cadd[512];
    int b = blockIdx.z, chunk = blockIdx.y * 512;
    int lane = threadIdx.x & 31, yg = threadIdx.x >> 5;
    for (int i = threadIdx.x; i < 512; i += 256)
        cadd[i] = Cmask[b * LC + chunk + i] ? 0.f : NEGF;
    __syncthreads();
    int q = blockIdx.x * 32 + lane, cl = yg * 64;
    const float* Sp = g_S + (size_t)b * LC * LQ + (size_t)(chunk + cl) * LQ + q;
    float m = -INFINITY, s = 0.f;
    #pragma unroll 4
    for (int i = 0; i < 16; i++) {
        const float* p = Sp + (size_t)i * 4 * LQ;
        float v0 = p[0] + cadd[cl + i * 4], v1 = p[LQ] + cadd[cl + i * 4 + 1];
        float v2 = p[2 * LQ] + cadd[cl + i * 4 + 2], v3 = p[3 * LQ] + cadd[cl + i * 4 + 3];
        float mn = fmaxf(m, fmaxf(fmaxf(v0, v1), fmaxf(v2, v3)));
        s = s * __expf(m - mn) + __expf(v0 - mn) + __expf(v1 - mn)
                               + __expf(v2 - mn) + __expf(v3 - mn);
        m = mn;
    }
    sm[yg][lane] = m; ss[yg][lane] = s;
    __syncthreads();
    if (yg == 0) {
        float M = m, S = s;
        #pragma unroll
        for (int g = 1; g < 8; g++) {
            float m2 = sm[g][lane], s2 = ss[g][lane], mn = fmaxf(M, m2);
            S = S * __expf(M - mn) + s2 * __expf(m2 - mn); M = mn;
        }
        int idx = (blockIdx.y * BB + b) * LQ + q;
        g_cpm[idx] = M; g_cps[idx] = S;
    }
}

__global__ void k_colstats_merge() {
    int t = blockIdx.x * 256 + threadIdx.x;
    if (t >= BB * LQ) return;
    float M = -INFINITY, S = 0.f;
    #pragma unroll
    for (int g = 0; g < 4; g++) {
        float m2 = g_cpm[g * BB * LQ + t], s2 = g_cps[g * BB * LQ + t], mn = fmaxf(M, m2);
        S = S * __expf(M - mn) + s2 * __expf(m2 - mn); M = mn;
    }
    g_cmax[t] = M; g_cinv[t] = 1.f / S;
}

// ============================================================
// K4: V2 partials [m=q, n=d, k=c]  A:T (exp S2), B:R (C)
// ============================================================
__global__ __launch_bounds__(256, 2) void k_gemmV2(const float* __restrict__ C,
                                                   const int* __restrict__ Cmask) {
    extern __shared__ uint32_t smu[];
    uint32_t* TAH = smu;
    uint32_t* TAL = TAH + TILE_U;
    uint32_t* TBH = TAL + TILE_U;
    uint32_t* TBL = TBH + TILE_U;
    float* AUX = (float*)(TBL + TILE_U);
    int tid = threadIdx.x, wid = tid >> 5, lane = tid & 31;
    int b = blockIdx.z, part = blockIdx.y, qb = blockIdx.x * 128;
    int mbase = (wid >> 1) * 32, nbase = (wid & 1) * 64;
    int c0chunk = part * 512;

    if (tid < 128) {
        AUX[tid] = g_cmax[b * LQ + qb + tid];
        AUX[128 + tid] = g_cinv[b * LQ + qb + tid];
    }
    for (int i = tid; i < 512; i += 256) AUX[256 + i] = Cmask[b * LC + c0chunk + i] ? 0.f : NEGF;
    __syncthreads();

    float acc[2][8][4];
    #pragma unroll
    for (int i = 0; i < 2; i++)
        #pragma unroll
        for (int j = 0; j < 8; j++)
            #pragma unroll
            for (int r = 0; r < 4; r++) acc[i][j][r] = 0.f;

    const float* Cb = C + (size_t)b * DD * LC;
    const float* Sb = g_S + ((size_t)b * LC + c0chunk) * LQ + qb;

    for (int k0 = 0; k0 < 512; k0 += 32) {
        // A: exp(S2) transposed, pairs along c
        #pragma unroll
        for (int it = 0; it < 4; it++) {
            int idx = tid + it * 256;
            int kp = idx & 15, qp = idx >> 4;
            int q2 = qp * 2;
            int cg = k0 + 2 * kp;
            float2 v0 = *(const float2*)(Sb + (size_t)cg * LQ + q2);
            float2 v1 = *(const float2*)(Sb + (size_t)(cg + 1) * LQ + q2);
            float ca0 = AUX[256 + cg], ca1 = AUX[256 + cg + 1];
            float e00 = __expf(v0.x + ca0 - AUX[q2]) * AUX[128 + q2];
            float e10 = __expf(v1.x + ca1 - AUX[q2]) * AUX[128 + q2];
            float e01 = __expf(v0.y + ca0 - AUX[q2 + 1]) * AUX[128 + q2 + 1];
            float e11 = __expf(v1.y + ca1 - AUX[q2 + 1]) * AUX[128 + q2 + 1];
            uint32_t H, L;
            split2(e00, e10, H, L);
            TAH[kp * TSTR2 + q2] = H; TAL[kp * TSTR2 + q2] = L;
            split2(e01, e11, H, L);
            TAH[kp * TSTR2 + q2 + 1] = H; TAL[kp * TSTR2 + q2 + 1] = L;
        }
        // B: C[d][c] with pairs along c
        #pragma unroll
        for (int p = 0; p < 4; p++) {
            int row = (tid >> 3) + p * 32;
            int cc = (tid & 7) * 4;
            int kp = (tid & 7) * 2;
            float4 w = *(const float4*)(Cb + (size_t)row * LC + c0chunk + k0 + cc);
            uint32_t H, L;
            split2(w.x, w.y, H, L);
            TBH[kp * TSTR2 + row] = H; TBL[kp * TSTR2 + row] = L;
            split2(w.z, w.w, H, L);
            TBH[(kp + 1) * TSTR2 + row] = H; TBL[(kp + 1) * TSTR2 + row] = L;
        }
        __syncthreads();
        mma_chunk(TAH, TAL, TBH, TBL, acc, mbase, nbase, lane);
        __syncthreads();
    }

    int lq = lane >> 2, kq = lane & 3;
    float* Vp = g_V2p + ((size_t)part * BB * LQ + (size_t)b * LQ + qb) * DD;
    #pragma unroll
    for (int ma = 0; ma < 2; ma++)
        #pragma unroll
        for (int na = 0; na < 8; na++) {
            int r = mbase + 16 * ma + lq;
            int col = nbase + 8 * na + kq * 2;
            *(float2*)(Vp + (size_t)r * DD + col) =
                make_float2(acc[ma][na][0], acc[ma][na][1]);
            *(float2*)(Vp + (size_t)(r + 8) * DD + col) =
                make_float2(acc[ma][na][2], acc[ma][na][3]);
        }
}

__global__ void k_reduceV2() {
    const int n = BB * LQ * DD / 4;
    int i = blockIdx.x * blockDim.x + threadIdx.x;
    if (i < n) {
        const float4* p = (const float4*)g_V2p;
        float4 a = p[i], b2 = p[i + n], c = p[i + 2 * n], d = p[i + 3 * n];
        float4 o;
        o.x = a.x + b2.x + c.x + d.x;
        o.y = a.y + b2.y + c.y + d.y;
        o.z = a.z + b2.z + c.z + d.z;
        o.w = a.w + b2.w + c.w + d.w;
        ((float4*)g_V2)[i] = o;
    }
}

// ============================================================
// K5: FUSED  A = S1 @ Qt  AND  Bmat = S1 @ V2   [m=c, n=d, k=q(512)]
// A-tiles (exp S1) filled ONCE per chunk, used for both products.
// ============================================================
__global__ __launch_bounds__(256, 1) void k_gemmAB(const float* __restrict__ Q,
                                                   const int* __restrict__ Qmask) {
    extern __shared__ uint32_t smu[];
    uint32_t* TAH = smu;
    uint32_t* TAL = TAH + TILE_U;
    uint32_t* TBH = TAL + TILE_U;
    uint32_t* TBL = TBH + TILE_U;
    float* AUX = (float*)(TBL + TILE_U);
    int tid = threadIdx.x, wid = tid >> 5, lane = tid & 31;
    int b = blockIdx.y, cb = blockIdx.x * 128;
    int mbase = (wid >> 1) * 32, nbase = (wid & 1) * 64;

    if (tid < 128) {
        AUX[tid] = g_rmax[b * LC + cb + tid];
        AUX[128 + tid] = g_rinv[b * LC + cb + tid];
    }
    for (int i = tid; i < 512; i += 256) AUX[256 + i] = Qmask[b * LQ + i] ? 0.f : NEGF;
    __syncthreads();

    float accA[2][8][4], accB[2][8][4];
    #pragma unroll
    for (int i = 0; i < 2; i++)
        #pragma unroll
        for (int j = 0; j < 8; j++)
            #pragma unroll
            for (int r = 0; r < 4; r++) { accA[i][j][r] = 0.f; accB[i][j][r] = 0.f; }

    const float* Sb = g_S + ((size_t)b * LC + cb) * LQ;
    const float* Qb = Q + (size_t)b * DD * LQ;
    const float* Vb = g_V2 + (size_t)b * LQ * DD;

    for (int k0 = 0; k0 < LQ; k0 += 32) {
        // A fill (exp S1, pairs along q) + B fill (Qt, pairs along q) — r6-gemmA verbatim
        #pragma unroll
        for (int p = 0; p < 4; p++) {
            int row = (tid >> 3) + p * 32;
            int qq = (tid & 7) * 4;
            int kp = (tid & 7) * 2;
            float4 v = *(const float4*)(Sb + (size_t)row * LQ + k0 + qq);
            float rm = AUX[row], ri = AUX[128 + row];
            float e0 = __expf(v.x + AUX[256 + k0 + qq + 0] - rm) * ri;
            float e1 = __expf(v.y + AUX[256 + k0 + qq + 1] - rm) * ri;
            float e2 = __expf(v.z + AUX[256 + k0 + qq + 2] - rm) * ri;
            float e3 = __expf(v.w + AUX[256 + k0 + qq + 3] - rm) * ri;
            uint32_t H, L;
            split2(e0, e1, H, L);
            TAH[kp * TSTR2 + row] = H; TAL[kp * TSTR2 + row] = L;
            split2(e2, e3, H, L);
            TAH[(kp + 1) * TSTR2 + row] = H; TAL[(kp + 1) * TSTR2 + row] = L;
            float4 w = *(const float4*)(Qb + (size_t)row * LQ + k0 + qq);
            split2(w.x, w.y, H, L);
            TBH[kp * TSTR2 + row] = H; TBL[kp * TSTR2 + row] = L;
            split2(w.z, w.w, H, L);
            TBH[(kp + 1) * TSTR2 + row] = H; TBL[(kp + 1) * TSTR2 + row] = L;
        }
        __syncthreads();
        mma_chunk(TAH, TAL, TBH, TBL, accA, mbase, nbase, lane);
        __syncthreads();
        // B fill with V2 (pairs along q) — r6-gemmB verbatim; A tiles untouched
        #pragma unroll
        for (int it = 0; it < 2; it++) {
            int idx = tid + it * 256;
            int kp = idx & 15, dp = idx >> 4;
            int d2 = dp * 4;
            int qg = k0 + 2 * kp;
            float4 v0 = *(const float4*)(Vb + (size_t)qg * DD + d2);
            float4 v1 = *(const float4*)(Vb + (size_t)(qg + 1) * DD + d2);
            uint32_t H, L;
            split2(v0.x, v1.x, H, L);
            TBH[kp * TSTR2 + d2] = H; TBL[kp * TSTR2 + d2] = L;
            split2(v0.y, v1.y, H, L);
            TBH[kp * TSTR2 + d2 + 1] = H; TBL[kp * TSTR2 + d2 + 1] = L;
            split2(v0.z, v1.z, H, L);
            TBH[kp * TSTR2 + d2 + 2] = H; TBL[kp * TSTR2 + d2 + 2] = L;
            split2(v0.w, v1.w, H, L);
            TBH[kp * TSTR2 + d2 + 3] = H; TBL[kp * TSTR2 + d2 + 3] = L;
        }
        __syncthreads();
        mma_chunk(TAH, TAL, TBH, TBL, accB, mbase, nbase, lane);
        __syncthreads();
    }

    int lq = lane >> 2, kq = lane & 3;
    float* Ab = g_A + ((size_t)b * LC + cb) * DD;
    float* Bmb = g_Bm + ((size_t)b * LC + cb) * DD;
    #pragma unroll
    for (int ma = 0; ma < 2; ma++)
        #pragma unroll
        for (int na = 0; na < 8; na++) {
            int r = mbase + 16 * ma + lq;
            int col = nbase + 8 * na + kq * 2;
            *(float2*)(Ab + (size_t)r * DD + col) =
                make_float2(accA[ma][na][0], accA[ma][na][1]);
            *(float2*)(Ab + (size_t)(r + 8) * DD + col) =
                make_float2(accA[ma][na][2], accA[ma][na][3]);
            *(float2*)(Bmb + (size_t)r * DD + col) =
                make_float2(accB[ma][na][0], accB[ma][na][1]);
            *(float2*)(Bmb + (size_t)(r + 8) * DD + col) =
                make_float2(accB[ma][na][2], accB[ma][na][3]);
        }
}

// ============================================================
// K6: assemble
// ============================================================
__global__ void k_assemble(const float* __restrict__ C, float* __restrict__ out) {
    __shared__ float As[32][33], Bs[32][33];
    int b = blockIdx.z, cb = blockIdx.x * 32, db = blockIdx.y * 32;
    int x = threadIdx.x, y = threadIdx.y;
    #pragma unroll
    for (int yy = 0; yy < 4; yy++) {
        int c = y + 8 * yy;
        As[c][x] = g_A[((size_t)b * LC + cb + c) * DD + db + x];
        Bs[c][x] = g_Bm[((size_t)b * LC + cb + c) * DD + db + x];
    }
    __syncthreads();
    #pragma unroll
    for (int yy = 0; yy < 4; yy++) {
        int d = y + 8 * yy;
        float cv = C[((size_t)b * DD + db + d) * LC + cb + x];
        float av = As[x][d], bv = Bs[x][d];
        size_t o = (size_t)b * 4 * DD * LC + cb + x;
        out[o + (size_t)(db + d) * LC] = cv;
        out[o + (size_t)(DD + db + d) * LC] = av;
        out[o + (size_t)(2 * DD + db + d) * LC] = cv * av;
        out[o + (size_t)(3 * DD + db + d) * LC] = cv * bv;
    }
}

extern "C" void kernel_launch(void* const* d_in, const int* in_sizes, int n_in,
                              void* d_out, int out_size) {
    const float* C = (const float*)d_in[0];
    const float* Q = (const float*)d_in[1];
    const int* Cmask = (const int*)d_in[2];
    const int* Qmask = (const int*)d_in[3];
    const float* w4C = (const float*)d_in[4];
    const float* w4Q = (const float*)d_in[5];
    const float* w4mlu = (const float*)d_in[6];
    const float* bias = (const float*)d_in[7];
    float* out = (float*)d_out;

    cudaFuncSetAttribute(k_scores, cudaFuncAttributeMaxDynamicSharedMemorySize, SMEM_BYTES);
    cudaFuncSetAttribute(k_gemmV2, cudaFuncAttributeMaxDynamicSharedMemorySize, SMEM_BYTES);
    cudaFuncSetAttribute(k_gemmAB, cudaFuncAttributeMaxDynamicSharedMemorySize, SMEM_BYTES);

    int nsub = BB * LC + BB * LQ;
    k_sub<<<(nsub + 255) / 256, 256>>>(C, Q, w4C, w4Q, bias);
    k_scores<<<dim3(4, 16, 16), 256, SMEM_BYTES>>>(C, Q, w4mlu);
    k_rowstats<<<(BB * LC) / 8, 256>>>(Qmask);
    k_colstats_part<<<dim3(16, 4, 16), 256>>>(Cmask);
    k_colstats_merge<<<32, 256>>>();
    k_gemmV2<<<dim3(4, 4, 16), 256, SMEM_BYTES>>>(C, Cmask);
    k_reduceV2<<<(BB * LQ * DD / 4 + 255) / 256, 256>>>();
    k_gemmAB<<<dim3(16, 16), 256, SMEM_BYTES>>>(Q, Qmask);
    k_assemble<<<dim3(64, 4, 16), dim3(32, 8)>>>(C, out);
}